// round 12
// baseline (speedup 1.0000x reference)
#include <cuda_runtime.h>
#include <cstdint>

// Problem dims
static constexpr int Bn = 8, Tn = 256, Un = 64, Dn = 512, Vn = 1024;
// Tiling
static constexpr int MT = 128;             // CTA m-tile
static constexpr int NT = 128;             // CTA n-tile
static constexpr int KC = 32;              // k-chunk (floats)
static constexpr int NKC = Dn / KC;        // 16
static constexpr int M_TOTAL = Bn * Tn * Un;        // 131072
static constexpr int MTILES  = M_TOTAL / MT;        // 1024
static constexpr int NTILES  = Vn / NT;             // 8
static constexpr int MAIN_OUT = M_TOTAL * Vn;       // 134217728

// Padded smem row stride (floats): 36 -> bank (4*row + k) % 32, conflict-free frags,
// and 144 B rows keep float4 / cp.async 16 B alignment.
static constexpr int PADS = 36;
static constexpr int BUF_F = 128 * PADS;            // floats per stage buffer (4608)
static constexpr int SMEM_TOTAL = 4 * BUF_F * 4;    // 2 A stages + 2 W stages = 73728 B

// W pre-converted to tf32 bit patterns, blocked [nt][kc][row(128)][col(32)] contiguous.
__device__ uint32_t g_W[(size_t)NTILES * NKC * MT * KC];   // 2 MB

// ---------------- helpers ----------------
__device__ __forceinline__ uint32_t smem_u32(const void* p) {
    uint32_t a;
    asm("{ .reg .u64 t; cvta.to.shared.u64 t, %1; cvt.u32.u64 %0, t; }" : "=r"(a) : "l"(p));
    return a;
}
__device__ __forceinline__ uint32_t f32_to_tf32(float f) {
    uint32_t r;
    asm("cvt.rna.tf32.f32 %0, %1;" : "=r"(r) : "f"(f));
    return r;
}
__device__ __forceinline__ void cp_async16(uint32_t smem_addr, const void* gptr) {
    asm volatile("cp.async.cg.shared.global [%0], [%1], 16;"
                 :: "r"(smem_addr), "l"(gptr) : "memory");
}
__device__ __forceinline__ void cp_commit() {
    asm volatile("cp.async.commit_group;" ::: "memory");
}
__device__ __forceinline__ void cp_wait_all() {
    asm volatile("cp.async.wait_all;" ::: "memory");
}
// m16n8k8 tf32 MMA: A row-major (16x8), B col-major (8x8), fp32 accumulate.
__device__ __forceinline__ void mma_tf32(float* d, const uint32_t* a, uint32_t b0, uint32_t b1) {
    asm volatile(
        "mma.sync.aligned.m16n8k8.row.col.f32.tf32.tf32.f32 "
        "{%0,%1,%2,%3}, {%4,%5,%6,%7}, {%8,%9}, {%0,%1,%2,%3};"
        : "+f"(d[0]), "+f"(d[1]), "+f"(d[2]), "+f"(d[3])
        : "r"(a[0]), "r"(a[1]), "r"(a[2]), "r"(a[3]), "r"(b0), "r"(b1));
}

// ---------------- prep kernel: W -> tf32 bits, blocked layout ----------------
__global__ void prep_w_kernel(const float* __restrict__ W) {
    int idx = blockIdx.x * blockDim.x + threadIdx.x;
    if (idx >= Vn * Dn) return;
    int v = idx >> 9;          // / Dn
    int d = idx & 511;
    int nt  = v >> 7;          // / NT
    int row = v & 127;
    int kc  = d >> 5;          // / KC
    int col = d & 31;
    g_W[(((size_t)nt * NKC + kc) << 12) + (row << 5) + col] = f32_to_tf32(W[idx]);
}

// ---------------- main kernel ----------------
__global__ __launch_bounds__(256)
void joiner_mma_kernel(const float* __restrict__ src,   // (B*T, D)
                       const float* __restrict__ tgt,   // (B*U, D)
                       const float* __restrict__ bias,  // (V,)
                       float* __restrict__ out)         // (B*T*U, V)
{
    extern __shared__ __align__(16) float smf[];
    // smem: A stage0 | A stage1 | W stage0 | W stage1, each BUF_F floats
    float* As_[2] = { smf,              smf + BUF_F };
    float* Ws_[2] = { smf + 2 * BUF_F,  smf + 3 * BUF_F };

    const int tid  = threadIdx.x;
    const int wid  = tid >> 5;
    const int lane = tid & 31;
    const int gid  = lane >> 2;   // 0..7
    const int tig  = lane & 3;    // 0..3
    const int warp_m = wid & 3;   // 4 m-warps (32 rows each)
    const int warp_n = wid >> 2;  // 2 n-warps (64 cols each)

    const int mt = blockIdx.x;
    const int nt = blockIdx.y;
    const int g0 = mt * 2;        // first of two 64-row u-groups; g = flattened b*T+t
    const int bb = g0 >> 8;       // batch (T = 256)

    // Per-thread copy-slot offsets (4 slots of 16 B each; 1024 slots cover a 16 KB chunk)
    int off_src[4], off_tgt[4], sts_off[4], wsrc_off[4];
    uint32_t wdst_addr[4];
#pragma unroll
    for (int i = 0; i < 4; i++) {
        const int sidx = tid + i * 256;       // 0..1023
        const int row  = sidx >> 3;           // 0..127
        const int seg  = sidx & 7;            // 0..7 (4-float segment)
        const int g    = g0 + (row >> 6);
        const int u    = row & 63;
        off_src[i] = g * Dn + seg * 4;                    // + d0
        off_tgt[i] = (bb * Un + u) * Dn + seg * 4;        // + d0
        sts_off[i] = row * PADS + seg * 4;                // smem float index
        wsrc_off[i] = sidx * 4;                           // float index within W chunk
        wdst_addr[i] = smem_u32(Ws_[0] + sts_off[i]);     // stage-0 byte address
    }
    const uint32_t wstage_bytes = BUF_F * 4;

    float acc[2][8][4];
#pragma unroll
    for (int a = 0; a < 2; a++)
#pragma unroll
        for (int b = 0; b < 8; b++)
#pragma unroll
            for (int c = 0; c < 4; c++) acc[a][b][c] = 0.0f;

    const size_t wchunk_base = ((size_t)nt * NKC) << 12;   // float idx of (nt, kc=0)

    // ---- Prologue: stage 0 for chunk 0 ----
#pragma unroll
    for (int i = 0; i < 4; i++)
        cp_async16(wdst_addr[i], g_W + wchunk_base + wsrc_off[i]);
    cp_commit();
    {
#pragma unroll
        for (int i = 0; i < 4; i++) {
            const float4 sv = *(const float4*)(src + off_src[i]);
            const float4 tv = *(const float4*)(tgt + off_tgt[i]);
            uint4 o;
            o.x = f32_to_tf32(fmaxf(sv.x + tv.x, 0.0f));
            o.y = f32_to_tf32(fmaxf(sv.y + tv.y, 0.0f));
            o.z = f32_to_tf32(fmaxf(sv.z + tv.z, 0.0f));
            o.w = f32_to_tf32(fmaxf(sv.w + tv.w, 0.0f));
            *(uint4*)(As_[0] + sts_off[i]) = o;
        }
    }
    cp_wait_all();
    __syncthreads();

    // ---- Main loop over 16 k-chunks, double buffered ----
#pragma unroll 1
    for (int kc = 0; kc < NKC; kc++) {
        const int cur = kc & 1;
        const int nxt = cur ^ 1;
        const bool pf = (kc + 1) < NKC;

        float4 s4[4], t4[4];
        if (pf) {
            const size_t wb = wchunk_base + ((size_t)(kc + 1) << 12);
#pragma unroll
            for (int i = 0; i < 4; i++)
                cp_async16(wdst_addr[i] + nxt * wstage_bytes, g_W + wb + wsrc_off[i]);
            cp_commit();
            const int d0 = (kc + 1) * KC;
#pragma unroll
            for (int i = 0; i < 4; i++) {
                s4[i] = *(const float4*)(src + off_src[i] + d0);
                t4[i] = *(const float4*)(tgt + off_tgt[i] + d0);
            }
        }

        // Compute on current buffers
        const uint32_t* As = (const uint32_t*)As_[cur];
        const uint32_t* Ws = (const uint32_t*)Ws_[cur];
#pragma unroll
        for (int ks = 0; ks < 4; ks++) {
            const int ko = ks * 8;
            uint32_t afr[2][4];
#pragma unroll
            for (int tm = 0; tm < 2; tm++) {
                const int rb = warp_m * 32 + tm * 16;
                afr[tm][0] = As[(rb + gid)     * PADS + ko + tig];
                afr[tm][1] = As[(rb + gid + 8) * PADS + ko + tig];
                afr[tm][2] = As[(rb + gid)     * PADS + ko + tig + 4];
                afr[tm][3] = As[(rb + gid + 8) * PADS + ko + tig + 4];
            }
#pragma unroll
            for (int tn = 0; tn < 8; tn++) {
                const int nr = warp_n * 64 + tn * 8 + gid;
                const uint32_t b0 = Ws[nr * PADS + ko + tig];
                const uint32_t b1 = Ws[nr * PADS + ko + tig + 4];
                mma_tf32(acc[0][tn], afr[0], b0, b1);
                mma_tf32(acc[1][tn], afr[1], b0, b1);
            }
        }

        if (pf) {
#pragma unroll
            for (int i = 0; i < 4; i++) {
                uint4 o;
                o.x = f32_to_tf32(fmaxf(s4[i].x + t4[i].x, 0.0f));
                o.y = f32_to_tf32(fmaxf(s4[i].y + t4[i].y, 0.0f));
                o.z = f32_to_tf32(fmaxf(s4[i].z + t4[i].z, 0.0f));
                o.w = f32_to_tf32(fmaxf(s4[i].w + t4[i].w, 0.0f));
                *(uint4*)(As_[nxt] + sts_off[i]) = o;
            }
            cp_wait_all();
        }
        __syncthreads();
    }

    // ---- Epilogue: registers -> global with bias ----
    const int mbase = mt * MT + warp_m * 32;
    const int nbase = nt * NT + warp_n * 64;
#pragma unroll
    for (int tn = 0; tn < 8; tn++) {
        const int c = nbase + tn * 8 + 2 * tig;
        const float2 bz = *(const float2*)(bias + c);
#pragma unroll
        for (int tm = 0; tm < 2; tm++) {
            const int r0 = mbase + tm * 16 + gid;
            float2 v0, v1;
            v0.x = acc[tm][tn][0] + bz.x;  v0.y = acc[tm][tn][1] + bz.y;
            v1.x = acc[tm][tn][2] + bz.x;  v1.y = acc[tm][tn][3] + bz.y;
            *(float2*)(out + (size_t)r0 * Vn + c) = v0;
            *(float2*)(out + (size_t)(r0 + 8) * Vn + c) = v1;
        }
    }
}

// Pass-through lengths if the harness concatenates the output tuple.
__global__ void tail_kernel(const int* __restrict__ sl, const int* __restrict__ tl,
                            float* __restrict__ dst, int n) {
    int i = threadIdx.x;
    if (i < n) {
        float v = 0.0f;
        if (i < 8) v = (float)sl[i];
        else if (i < 16) v = (float)tl[i - 8];
        dst[i] = v;
    }
}

extern "C" void kernel_launch(void* const* d_in, const int* in_sizes, int n_in,
                              void* d_out, int out_size) {
    const float* src  = (const float*)d_in[0];   // (B,T,D) f32
    const int*   slen = (const int*)d_in[1];     // (B,) i32
    const float* tgt  = (const float*)d_in[2];   // (B,U,D) f32
    const int*   tlen = (const int*)d_in[3];     // (B,) i32
    const float* W    = (const float*)d_in[4];   // (V,D) f32
    const float* bias = (const float*)d_in[5];   // (V,) f32
    float* out = (float*)d_out;

    (void)in_sizes; (void)n_in;

    // 1) Convert W -> tf32 bits in blocked layout (~4 MB traffic, trivial)
    prep_w_kernel<<<(Vn * Dn + 255) / 256, 256>>>(W);

    // 2) Fused relu-add GEMM (mma.sync tf32)
    cudaFuncSetAttribute(joiner_mma_kernel, cudaFuncAttributeMaxDynamicSharedMemorySize,
                         SMEM_TOTAL);
    dim3 grid(MTILES, NTILES);
    joiner_mma_kernel<<<grid, 256, SMEM_TOTAL>>>(src, tgt, bias, out);

    // 3) Optional pass-through lengths
    int extra = out_size - MAIN_OUT;
    if (extra > 0) {
        if (extra > 32) extra = 32;
        tail_kernel<<<1, 32>>>(slen, tlen, out + MAIN_OUT, extra);
    }
}